// round 1
// baseline (speedup 1.0000x reference)
#include <cuda_runtime.h>
#include <cuda_bf16.h>

#define HH 2048
#define NPIX (HH*HH)
#define NB 256
#define NRC 12   // 4 regions * 3 channels

// ---------------- global scratch (allocation-free: __device__ arrays) ----------------
__device__ unsigned g_hist_src[NRC*NB];
__device__ unsigned g_hist_tar[NRC*NB];
__device__ unsigned g_cnt[NRC*NB];
__device__ double   g_sum[NRC*NB];
__device__ double   g_loss;

// label -> region id maps (region: 0=face,1=hair,2=eye_l,3=eye_r, -1=none)
// src face labels: {1,7,8,10,11,14}; tar face labels: {1,7,8,10,14} (NO 11 — the
// reference's "bug" adds mask_A==11 to the tar face mask separately).
__constant__ signed char c_src[19] =
    {-1, 0, 2, 3, 2, 3,-1, 0, 0,-1, 0, 0,-1,-1, 0,-1,-1, 1,-1};
__constant__ signed char c_tar[19] =
    {-1, 0, 2, 3, 2, 3,-1, 0, 0,-1, 0,-1,-1,-1, 0,-1,-1, 1,-1};

__device__ __forceinline__ float denorm255(float x) {
    return __saturatef((x + 1.0f) * 0.5f) * 255.0f;
}
__device__ __forceinline__ int cdf_bin(float v) {
    // replicate: clip(floor(v * (256/255)), 0, 255); v >= 0 always here
    int b = (int)floorf(v * (float)(256.0 / 255.0));
    return b > 255 ? 255 : b;
}

// ---------------- init: zero scratch every launch (graph replay safe) ----------------
__global__ void hm_init() {
    int i = blockIdx.x * blockDim.x + threadIdx.x;
    if (i < NRC*NB) {
        g_hist_src[i] = 0u;
        g_hist_tar[i] = 0u;
        g_cnt[i]      = 0u;
        g_sum[i]      = 0.0;
    }
    if (i == 0) g_loss = 0.0;
}

// ---------------- pass 1: histograms + per-idx (cnt, sum) in one streaming pass ------
__device__ __forceinline__ void proc_pixel(
    int la, int lb, float f0, float f1, float f2, float r0, float r1, float r2,
    unsigned* shs, unsigned* sht, unsigned* shc, float* shv)
{
    int rs = ((unsigned)la < 19u) ? c_src[la] : -1;
    int rt = ((unsigned)lb < 19u) ? c_tar[lb] : -1;
    bool extra = (la == 11);            // reference bug: mask_B_face += (mask_A == 11)

    if (rs >= 0) {
        float vf[3] = {denorm255(f0), denorm255(f1), denorm255(f2)};
        int base = rs * 3 * NB;
        #pragma unroll
        for (int c = 0; c < 3; c++) {
            float v = vf[c];
            atomicAdd(&shs[base + c*NB + cdf_bin(v)], 1u);
            int idx = (int)v; if (idx > 255) idx = 255;
            atomicAdd(&shc[base + c*NB + idx], 1u);
            atomicAdd(&shv[base + c*NB + idx], v);
        }
    }

    int faceM = ((rt == 0) ? 1 : 0) + (extra ? 1 : 0);
    if (faceM | (rt > 0)) {
        float vr[3] = {denorm255(r0), denorm255(r1), denorm255(r2)};
        if (faceM) {
            float m = (float)faceM;     // mask value can be 2 (doubles the binned value)
            #pragma unroll
            for (int c = 0; c < 3; c++)
                atomicAdd(&sht[c*NB + cdf_bin(vr[c] * m)], 1u);
        }
        if (rt > 0) {
            int base = rt * 3 * NB;
            #pragma unroll
            for (int c = 0; c < 3; c++)
                atomicAdd(&sht[base + c*NB + cdf_bin(vr[c])], 1u);
        }
    }
}

__global__ void hm_pass1(const float* __restrict__ fa, const float* __restrict__ rb,
                         const int* __restrict__ ma, const int* __restrict__ mb)
{
    __shared__ unsigned shs[NRC*NB];
    __shared__ unsigned sht[NRC*NB];
    __shared__ unsigned shc[NRC*NB];
    __shared__ float    shv[NRC*NB];

    for (int i = threadIdx.x; i < NRC*NB; i += blockDim.x) {
        shs[i] = 0u; sht[i] = 0u; shc[i] = 0u; shv[i] = 0.0f;
    }
    __syncthreads();

    const int4*   ma4 = (const int4*)ma;
    const int4*   mb4 = (const int4*)mb;
    const float4* fa4 = (const float4*)fa;
    const float4* rb4 = (const float4*)rb;
    const int n4 = NPIX / 4;

    for (int g = blockIdx.x * blockDim.x + threadIdx.x; g < n4;
         g += gridDim.x * blockDim.x)
    {
        int4   a  = ma4[g];
        int4   b  = mb4[g];
        float4 f0 = fa4[g];
        float4 f1 = fa4[g +     n4];
        float4 f2 = fa4[g + 2 * n4];
        float4 r0 = rb4[g];
        float4 r1 = rb4[g +     n4];
        float4 r2 = rb4[g + 2 * n4];

        proc_pixel(a.x, b.x, f0.x, f1.x, f2.x, r0.x, r1.x, r2.x, shs, sht, shc, shv);
        proc_pixel(a.y, b.y, f0.y, f1.y, f2.y, r0.y, r1.y, r2.y, shs, sht, shc, shv);
        proc_pixel(a.z, b.z, f0.z, f1.z, f2.z, r0.z, r1.z, r2.z, shs, sht, shc, shv);
        proc_pixel(a.w, b.w, f0.w, f1.w, f2.w, r0.w, r1.w, r2.w, shs, sht, shc, shv);
    }
    __syncthreads();

    for (int i = threadIdx.x; i < NRC*NB; i += blockDim.x) {
        if (shs[i]) atomicAdd(&g_hist_src[i], shs[i]);
        if (sht[i]) atomicAdd(&g_hist_tar[i], sht[i]);
        if (shc[i]) atomicAdd(&g_cnt[i],      shc[i]);
        if (shv[i] != 0.0f) atomicAdd(&g_sum[i], (double)shv[i]);
    }
}

// ---------------- pass 2: CDFs, transfer table, closed-form loss ---------------------
__global__ void hm_pass2() {
    int rc = blockIdx.x;              // 0..11 = region*3 + channel
    int i  = threadIdx.x;             // 0..255

    __shared__ unsigned hs[NB], ht[NB];
    __shared__ float    dc[NB], ac[NB];
    __shared__ double   red[NB];

    hs[i] = g_hist_src[rc*NB + i];
    ht[i] = g_hist_tar[rc*NB + i];
    __syncthreads();

    // sequential f32 normalized cumsum (mirrors hist/max(sum,1) then cumsum in f32)
    if (i == 0) {
        unsigned tot = 0;
        for (int j = 0; j < NB; j++) tot += hs[j];
        float den = fmaxf((float)tot, 1.0f);
        float c = 0.0f;
        for (int j = 0; j < NB; j++) { c += (float)hs[j] / den; dc[j] = c; }
    }
    if (i == 1 || (blockDim.x == NB && i == 32)) { /* no-op to keep single writer */ }
    if (i == (NB > 32 ? 32 : 0)) {
        unsigned tot = 0;
        for (int j = 0; j < NB; j++) tot += ht[j];
        float den = fmaxf((float)tot, 1.0f);
        float c = 0.0f;
        for (int j = 0; j < NB; j++) { c += (float)ht[j] / den; ac[j] = c; }
    }
    __syncthreads();

    // cal_trans: first j in 1..255 with ac[j-1] <= dc[i] <= ac[j], else i; endpoints pinned
    int t;
    if (i == 0)        t = 0;
    else if (i == 255) t = 255;
    else {
        float d = dc[i];
        t = i;
        for (int j = 1; j < NB; j++) {
            if (d >= ac[j-1] && d <= ac[j]) { t = j; break; }
        }
    }

    // loss contribution: v in [i, i+1) so sign of (v - t) is fixed by (t <= i)
    unsigned cnt = g_cnt[rc*NB + i];
    double   s   = g_sum[rc*NB + i];
    double   T   = (double)t;
    double contrib = (t <= i) ? (s - (double)cnt * T) : ((double)cnt * T - s);
    red[i] = contrib;
    __syncthreads();

    for (int off = NB/2; off > 0; off >>= 1) {
        if (i < off) red[i] += red[i + off];
        __syncthreads();
    }
    if (i == 0) atomicAdd(&g_loss, red[0]);
}

// ---------------- finalize -----------------------------------------------------------
__global__ void hm_finalize(float* out) {
    // loss = 0.1*(face+hair+eye_l+eye_r) means, all lambdas equal 0.1
    out[0] = (float)(0.1 * g_loss / (3.0 * (double)NPIX));
}

extern "C" void kernel_launch(void* const* d_in, const int* in_sizes, int n_in,
                              void* d_out, int out_size)
{
    const float* fake_A = (const float*)d_in[0];
    const float* ref_B  = (const float*)d_in[1];
    const int*   mask_A = (const int*)d_in[2];
    const int*   mask_B = (const int*)d_in[3];
    float* out = (float*)d_out;

    hm_init<<<(NRC*NB + 255) / 256, 256>>>();
    hm_pass1<<<592, 256>>>(fake_A, ref_B, mask_A, mask_B);
    hm_pass2<<<NRC, NB>>>();
    hm_finalize<<<1, 1>>>(out);
}